// round 2
// baseline (speedup 1.0000x reference)
#include <cuda_runtime.h>

#define NC   200
#define S3   76800      // 16*60*80
#define S2   19200      // 120*160
#define NV   129600     // 60*60*36
#define NB   2

// Scratch (allocation-free contract: __device__ globals)
__device__ float  g_X3[NB * S3 * NC];   // [b][cell][c]  = x3a+x3b transposed, ~123 MB
__device__ float  g_X2[NB * S2 * NC];   // [b][pix][c]   = x2a+x2b transposed, ~31 MB
__device__ float4 g_s3[NB * NV];        // wx,wy,wz, packed(x0,y0,z0)
__device__ float4 g_s2[NB * NV];        // wx,wy, packed(x0,y0), -

// ---------------------------------------------------------------------------
// Sum + transpose: in [b][c][s] (+ second input) -> out [b][s][c]
// which==0 -> g_X3, which==1 -> g_X2
// ---------------------------------------------------------------------------
__global__ void sum_transpose_kernel(const float* __restrict__ a,
                                     const float* __restrict__ b2,
                                     int S, int which)
{
    __shared__ float tile[32][33];
    float* outp = (which == 0) ? g_X3 : g_X2;
    int s0 = blockIdx.x * 32;
    int c0 = blockIdx.y * 32;
    int bb = blockIdx.z;
    int tx = threadIdx.x, ty = threadIdx.y;

    #pragma unroll
    for (int j = 0; j < 4; j++) {
        int c = c0 + ty + j * 8;
        if (c < NC) {
            int idx = (bb * NC + c) * S + s0 + tx;   // coalesced along s
            tile[ty + j * 8][tx] = a[idx] + b2[idx];
        }
    }
    __syncthreads();
    #pragma unroll
    for (int j = 0; j < 4; j++) {
        int s = s0 + ty + j * 8;
        int c = c0 + tx;
        if (c < NC)
            outp[(bb * S + s) * NC + c] = tile[tx][ty + j * 8]; // coalesced along c
    }
}

// ---------------------------------------------------------------------------
// Per-voxel sample-parameter precompute (once per voxel, shared by 200 ch)
// ---------------------------------------------------------------------------
__global__ void prep_kernel(const float* __restrict__ proj)
{
    int i = blockIdx.x * blockDim.x + threadIdx.x;
    if (i >= NB * NV) return;

    float px = proj[3 * i + 0];
    float py = proj[3 * i + 1];
    float pz = proj[3 * i + 2];

    // 3D: W=80, H=60, D=16
    float gx = (px + 1.0f) * 0.5f * 79.0f;
    float gy = (py + 1.0f) * 0.5f * 59.0f;
    float gz = (pz + 1.0f) * 0.5f * 15.0f;
    float fx = floorf(gx), fy = floorf(gy), fz = floorf(gz);
    float wx = gx - fx, wy = gy - fy, wz = gz - fz;
    int x0 = max(0, min(79, (int)fx));
    int y0 = max(0, min(59, (int)fy));
    int z0 = max(0, min(15, (int)fz));
    int packed3 = x0 | (y0 << 7) | (z0 << 13);
    g_s3[i] = make_float4(wx, wy, wz, __int_as_float(packed3));

    // 2D: W=160, H=120
    float hx = (px + 1.0f) * 0.5f * 159.0f;
    float hy = (py + 1.0f) * 0.5f * 119.0f;
    float fu = floorf(hx), fv = floorf(hy);
    float wu = hx - fu, wv = hy - fv;
    int u0 = max(0, min(159, (int)fu));
    int v0 = max(0, min(119, (int)fv));
    int packed2 = u0 | (v0 << 8);
    g_s2[i] = make_float4(wu, wv, __int_as_float(packed2), 0.0f);
}

// ---------------------------------------------------------------------------
// Main fused gather kernel.
// Block = (b, x, y, c-half). 60 z-voxels x 100 channels per block.
// Phase 1: gather 12 taps per (voxel, 2ch) item, coalesced float2 along c.
// Phase 2: write transposed output as contiguous 60-float z-rows per channel.
// ---------------------------------------------------------------------------
__global__ void __launch_bounds__(256) flosp_kernel(float* __restrict__ out)
{
    __shared__ float sAcc[60 * 101];   // [z][cl] padded (101 odd -> no bank conflicts)
    __shared__ int   sB[60 * 12];      // tap base offsets per voxel
    __shared__ float sW[60 * 12];      // tap weights per voxel

    int bid = blockIdx.x;
    int h   = bid & 1;                 // channel half: c in [h*100, h*100+100)
    int t2  = bid >> 1;                // b*2160 + x*36 + y
    int y   = t2 % 36;
    int t3  = t2 / 36;
    int x   = t3 % 60;
    int bb  = t3 / 60;
    int tid = threadIdx.x;

    if (tid < 60) {
        int z = tid;
        int v = (x * 60 + z) * 36 + y;
        float4 s3 = g_s3[bb * NV + v];
        float4 s2 = g_s2[bb * NV + v];

        int p3 = __float_as_int(s3.w);
        int x0 = p3 & 127, y0 = (p3 >> 7) & 63, z0 = (p3 >> 13) & 15;
        float wx = s3.x, wy = s3.y, wz = s3.z;
        float ux = 1.0f - wx, uy = 1.0f - wy, uz = 1.0f - wz;
        int base3 = (bb * S3 + (z0 * 60 + y0) * 80 + x0) * NC;
        int ox = (x0 < 79) ? NC        : 0;
        int oy = (y0 < 59) ? 80 * NC   : 0;
        int oz = (z0 < 15) ? 4800 * NC : 0;
        #pragma unroll
        for (int i = 0; i < 8; i++) {
            int dx = i & 1, dy = (i >> 1) & 1, dz = (i >> 2) & 1;
            sB[z * 12 + i] = base3 + (dx ? ox : 0) + (dy ? oy : 0) + (dz ? oz : 0);
            sW[z * 12 + i] = (dx ? wx : ux) * (dy ? wy : uy) * (dz ? wz : uz);
        }

        int p2 = __float_as_int(s2.z);
        int u0 = p2 & 255, v0 = (p2 >> 8) & 127;
        float wu = s2.x, wv = s2.y;
        float nu = 1.0f - wu, nv = 1.0f - wv;
        int base2 = (bb * S2 + v0 * 160 + u0) * NC;
        int ou = (u0 < 159) ? NC       : 0;
        int ov = (v0 < 119) ? 160 * NC : 0;
        #pragma unroll
        for (int j = 0; j < 4; j++) {
            int dx = j & 1, dy = j >> 1;
            sB[z * 12 + 8 + j] = base2 + (dx ? ou : 0) + (dy ? ov : 0);
            sW[z * 12 + 8 + j] = (dx ? wu : nu) * (dy ? wv : nv);
        }
    }
    __syncthreads();

    // Phase 1: 60 voxels * 50 float2-channel items = 3000 items
    for (int o = tid; o < 3000; o += 256) {
        int z = o / 50;
        int q = o - z * 50;
        int c = h * 100 + q * 2;
        const int*   Bv = sB + z * 12;
        const float* Wv = sW + z * 12;
        float a0 = 0.0f, a1 = 0.0f;
        #pragma unroll
        for (int i = 0; i < 8; i++) {
            float2 t = *(const float2*)&g_X3[Bv[i] + c];
            a0 += Wv[i] * t.x;
            a1 += Wv[i] * t.y;
        }
        #pragma unroll
        for (int i = 8; i < 12; i++) {
            float2 t = *(const float2*)&g_X2[Bv[i] + c];
            a0 += Wv[i] * t.x;
            a1 += Wv[i] * t.y;
        }
        sAcc[z * 101 + q * 2 + 0] = a0;
        sAcc[z * 101 + q * 2 + 1] = a1;
    }
    __syncthreads();

    // Phase 2: transposed write. out[b][c][x][y][z], z contiguous per channel.
    int obase = bb * (NC * NV) + (x * 36 + y) * 60;
    for (int o = tid; o < 6000; o += 256) {
        int cl = o / 60;
        int z  = o - cl * 60;
        int c  = h * 100 + cl;
        out[obase + c * NV + z] = sAcc[z * 101 + cl];
    }
}

// ---------------------------------------------------------------------------
extern "C" void kernel_launch(void* const* d_in, const int* in_sizes, int n_in,
                              void* d_out, int out_size)
{
    const float* x3a  = (const float*)d_in[0];
    const float* x3b  = (const float*)d_in[1];
    const float* x2a  = (const float*)d_in[2];
    const float* x2b  = (const float*)d_in[3];
    const float* proj = (const float*)d_in[4];
    float* out = (float*)d_out;

    dim3 tb(32, 8);
    sum_transpose_kernel<<<dim3(S3 / 32, 7, NB), tb>>>(x3a, x3b, S3, 0);
    sum_transpose_kernel<<<dim3(S2 / 32, 7, NB), tb>>>(x2a, x2b, S2, 1);
    prep_kernel<<<(NB * NV + 255) / 256, 256>>>(proj);
    flosp_kernel<<<NB * 60 * 36 * 2, 256>>>(out);
}

// round 5
// speedup vs baseline: 1.6466x; 1.6466x over previous
#include <cuda_runtime.h>
#include <cuda_fp16.h>

#define NC   200
#define S3   76800      // 16*60*80
#define S2   19200      // 120*160
#define NV   129600     // 60*60*36
#define NB   2

// Scratch (allocation-free contract: __device__ globals)
__device__ __half  g_X3[NB * S3 * NC];  // [b][cell][c]  fp16, 61.4 MB
__device__ __half  g_X2[NB * S2 * NC];  // [b][pix][c]   fp16, 15.4 MB
__device__ float4  g_s3[NB * NV];       // wx,wy,wz, packed(x0,y0,z0)
__device__ float4  g_s2[NB * NV];       // wx,wy, packed(x0,y0), -

// ---------------------------------------------------------------------------
// Sum + transpose + fp16 quantize: in [b][c][s] -> out [b][s][c] (half)
// ---------------------------------------------------------------------------
__global__ void sum_transpose_kernel(const float* __restrict__ a,
                                     const float* __restrict__ b2,
                                     int S, int which)
{
    __shared__ float tile[64][33];              // [c_local][s_local]
    __half* outp = (which == 0) ? g_X3 : g_X2;
    int s0 = blockIdx.x * 32;
    int c0 = blockIdx.y * 64;
    int bb = blockIdx.z;
    int tx = threadIdx.x, ty = threadIdx.y;     // 32 x 8

    #pragma unroll
    for (int j = 0; j < 8; j++) {
        int c = c0 + ty + j * 8;
        if (c < NC) {
            int idx = (bb * NC + c) * S + s0 + tx;       // coalesced along s
            tile[ty + j * 8][tx] = a[idx] + b2[idx];
        }
    }
    __syncthreads();
    int c = c0 + 2 * tx;
    if (c < NC) {
        #pragma unroll
        for (int j = 0; j < 4; j++) {
            int s = s0 + ty + j * 8;
            __half2 v = __floats2half2_rn(tile[2 * tx][ty + j * 8],
                                          tile[2 * tx + 1][ty + j * 8]);
            *(__half2*)&outp[(bb * S + s) * NC + c] = v;  // coalesced along c
        }
    }
}

// ---------------------------------------------------------------------------
// Per-voxel sample-parameter precompute (once per voxel, shared by 200 ch)
// ---------------------------------------------------------------------------
__global__ void prep_kernel(const float* __restrict__ proj)
{
    int i = blockIdx.x * blockDim.x + threadIdx.x;
    if (i >= NB * NV) return;

    float px = proj[3 * i + 0];
    float py = proj[3 * i + 1];
    float pz = proj[3 * i + 2];

    // 3D: W=80, H=60, D=16
    float gx = (px + 1.0f) * 0.5f * 79.0f;
    float gy = (py + 1.0f) * 0.5f * 59.0f;
    float gz = (pz + 1.0f) * 0.5f * 15.0f;
    float fx = floorf(gx), fy = floorf(gy), fz = floorf(gz);
    float wx = gx - fx, wy = gy - fy, wz = gz - fz;
    int x0 = max(0, min(79, (int)fx));
    int y0 = max(0, min(59, (int)fy));
    int z0 = max(0, min(15, (int)fz));
    int packed3 = x0 | (y0 << 7) | (z0 << 13);
    g_s3[i] = make_float4(wx, wy, wz, __int_as_float(packed3));

    // 2D: W=160, H=120
    float hx = (px + 1.0f) * 0.5f * 159.0f;
    float hy = (py + 1.0f) * 0.5f * 119.0f;
    float fu = floorf(hx), fv = floorf(hy);
    float wu = hx - fu, wv = hy - fv;
    int u0 = max(0, min(159, (int)fu));
    int v0 = max(0, min(119, (int)fv));
    int packed2 = u0 | (v0 << 8);
    g_s2[i] = make_float4(wu, wv, __int_as_float(packed2), 0.0f);
}

// ---------------------------------------------------------------------------
// Main fused gather kernel.
// Block = (b, x, y, c-half). 60 z-voxels x 100 channels per block.
// Phase 1: per item (z, 4 channels): 12 independent LDG.64 fp16 gathers.
// Phase 2: float4 transposed writes: z-contiguous 240B rows per channel.
// ---------------------------------------------------------------------------
__global__ void __launch_bounds__(256) flosp_kernel(float* __restrict__ out)
{
    __shared__ float sAcc[60 * 102];   // [z][cl], stride 102 (8B-aligned, low conflict)
    __shared__ int   sB[60 * 12];      // tap base offsets (in half-elements)
    __shared__ float sW[60 * 12];      // tap weights

    int bid = blockIdx.x;
    int h   = bid & 1;                 // channel half: c in [h*100, h*100+100)
    int t2  = bid >> 1;                // b*2160 + x*36 + y   (b major -> L2 phases)
    int y   = t2 % 36;
    int t3  = t2 / 36;
    int x   = t3 % 60;
    int bb  = t3 / 60;
    int tid = threadIdx.x;

    if (tid < 60) {
        int z = tid;
        int v = (x * 60 + z) * 36 + y;
        float4 s3 = g_s3[bb * NV + v];
        float4 s2 = g_s2[bb * NV + v];

        int p3 = __float_as_int(s3.w);
        int x0 = p3 & 127, y0 = (p3 >> 7) & 63, z0 = (p3 >> 13) & 15;
        float wx = s3.x, wy = s3.y, wz = s3.z;
        float ux = 1.0f - wx, uy = 1.0f - wy, uz = 1.0f - wz;
        int base3 = (bb * S3 + (z0 * 60 + y0) * 80 + x0) * NC;
        int ox = (x0 < 79) ? NC        : 0;
        int oy = (y0 < 59) ? 80 * NC   : 0;
        int oz = (z0 < 15) ? 4800 * NC : 0;
        #pragma unroll
        for (int i = 0; i < 8; i++) {
            int dx = i & 1, dy = (i >> 1) & 1, dz = (i >> 2) & 1;
            sB[z * 12 + i] = base3 + (dx ? ox : 0) + (dy ? oy : 0) + (dz ? oz : 0);
            sW[z * 12 + i] = (dx ? wx : ux) * (dy ? wy : uy) * (dz ? wz : uz);
        }

        int p2 = __float_as_int(s2.z);
        int u0 = p2 & 255, v0 = (p2 >> 8) & 127;
        float wu = s2.x, wv = s2.y;
        float nu = 1.0f - wu, nv = 1.0f - wv;
        int base2 = (bb * S2 + v0 * 160 + u0) * NC;
        int ou = (u0 < 159) ? NC       : 0;
        int ov = (v0 < 119) ? 160 * NC : 0;
        #pragma unroll
        for (int j = 0; j < 4; j++) {
            int dx = j & 1, dy = j >> 1;
            sB[z * 12 + 8 + j] = base2 + (dx ? ou : 0) + (dy ? ov : 0);
            sW[z * 12 + 8 + j] = (dx ? wu : nu) * (dy ? wv : nv);
        }
    }
    __syncthreads();

    int h100 = h * 100;

    // Phase 1: 60 voxels * 25 four-channel items = 1500 items
    for (int o = tid; o < 1500; o += 256) {
        int z = o / 25;
        int q = o - z * 25;
        int c = h100 + 4 * q;
        const int*   Bv = sB + z * 12;
        const float* Wv = sW + z * 12;
        float a0 = 0.f, a1 = 0.f, a2 = 0.f, a3 = 0.f;
        #pragma unroll
        for (int i = 0; i < 8; i++) {
            uint2 r = *(const uint2*)(g_X3 + Bv[i] + c);    // LDG.64, 4 halfs
            float2 f0 = __half22float2(*(__half2*)&r.x);
            float2 f1 = __half22float2(*(__half2*)&r.y);
            float w = Wv[i];
            a0 += w * f0.x; a1 += w * f0.y; a2 += w * f1.x; a3 += w * f1.y;
        }
        #pragma unroll
        for (int i = 8; i < 12; i++) {
            uint2 r = *(const uint2*)(g_X2 + Bv[i] + c);
            float2 f0 = __half22float2(*(__half2*)&r.x);
            float2 f1 = __half22float2(*(__half2*)&r.y);
            float w = Wv[i];
            a0 += w * f0.x; a1 += w * f0.y; a2 += w * f1.x; a3 += w * f1.y;
        }
        float* dst = &sAcc[z * 102 + 4 * q];
        *(float2*)(dst)     = make_float2(a0, a1);
        *(float2*)(dst + 2) = make_float2(a2, a3);
    }
    __syncthreads();

    // Phase 2: float4 transposed writes. out[b][c][x][y][z], 15 float4 per channel.
    int obase = bb * (NC * NV) + (x * 36 + y) * 60;
    for (int o = tid; o < 1500; o += 256) {
        int cl = o / 15;
        int zq = o - cl * 15;
        int c  = h100 + cl;
        float4 v;
        v.x = sAcc[(4 * zq + 0) * 102 + cl];
        v.y = sAcc[(4 * zq + 1) * 102 + cl];
        v.z = sAcc[(4 * zq + 2) * 102 + cl];
        v.w = sAcc[(4 * zq + 3) * 102 + cl];
        *(float4*)&out[obase + c * NV + 4 * zq] = v;
    }
}

// ---------------------------------------------------------------------------
extern "C" void kernel_launch(void* const* d_in, const int* in_sizes, int n_in,
                              void* d_out, int out_size)
{
    const float* x3a  = (const float*)d_in[0];
    const float* x3b  = (const float*)d_in[1];
    const float* x2a  = (const float*)d_in[2];
    const float* x2b  = (const float*)d_in[3];
    const float* proj = (const float*)d_in[4];
    float* out = (float*)d_out;

    dim3 tb(32, 8);
    sum_transpose_kernel<<<dim3(S3 / 32, 4, NB), tb>>>(x3a, x3b, S3, 0);
    sum_transpose_kernel<<<dim3(S2 / 32, 4, NB), tb>>>(x2a, x2b, S2, 1);
    prep_kernel<<<(NB * NV + 255) / 256, 256>>>(proj);
    flosp_kernel<<<NB * 60 * 36 * 2, 256>>>(out);
}

// round 6
// speedup vs baseline: 2.3523x; 1.4285x over previous
#include <cuda_runtime.h>
#include <cuda_fp16.h>

#define NC   200
#define S3   76800      // 16*60*80
#define S2   19200      // 120*160
#define NV   129600     // 60*60*36
#define NB   2
#define ZB   30         // z-voxels per block
#define ASTR 225        // sAcc row stride (odd -> conflict-free skewed layout)

// Scratch (allocation-free contract: __device__ globals)
__device__ __half  g_X3[NB * S3 * NC];  // [b][cell][c]  fp16, 61.4 MB
__device__ __half  g_X2[NB * S2 * NC];  // [b][pix][c]   fp16, 15.4 MB
__device__ float4  g_s3[NB * NV];       // wx,wy,wz, packed(x0,y0,z0)
__device__ float4  g_s2[NB * NV];       // wx,wy, packed(x0,y0), -

// ---------------------------------------------------------------------------
// Sum + transpose + fp16 quantize: in [b][c][s] -> out [b][s][c] (half)
// ---------------------------------------------------------------------------
__global__ void sum_transpose_kernel(const float* __restrict__ a,
                                     const float* __restrict__ b2,
                                     int S, int which)
{
    __shared__ float tile[64][33];              // [c_local][s_local]
    __half* outp = (which == 0) ? g_X3 : g_X2;
    int s0 = blockIdx.x * 32;
    int c0 = blockIdx.y * 64;
    int bb = blockIdx.z;
    int tx = threadIdx.x, ty = threadIdx.y;     // 32 x 8

    #pragma unroll
    for (int j = 0; j < 8; j++) {
        int c = c0 + ty + j * 8;
        if (c < NC) {
            int idx = (bb * NC + c) * S + s0 + tx;       // coalesced along s
            tile[ty + j * 8][tx] = a[idx] + b2[idx];
        }
    }
    __syncthreads();
    int c = c0 + 2 * tx;
    if (c < NC) {
        #pragma unroll
        for (int j = 0; j < 4; j++) {
            int s = s0 + ty + j * 8;
            __half2 v = __floats2half2_rn(tile[2 * tx][ty + j * 8],
                                          tile[2 * tx + 1][ty + j * 8]);
            *(__half2*)&outp[(bb * S + s) * NC + c] = v;  // coalesced along c
        }
    }
}

// ---------------------------------------------------------------------------
// Per-voxel sample-parameter precompute (once per voxel, shared by 200 ch)
// ---------------------------------------------------------------------------
__global__ void prep_kernel(const float* __restrict__ proj)
{
    int i = blockIdx.x * blockDim.x + threadIdx.x;
    if (i >= NB * NV) return;

    float px = proj[3 * i + 0];
    float py = proj[3 * i + 1];
    float pz = proj[3 * i + 2];

    // 3D: W=80, H=60, D=16
    float gx = (px + 1.0f) * 0.5f * 79.0f;
    float gy = (py + 1.0f) * 0.5f * 59.0f;
    float gz = (pz + 1.0f) * 0.5f * 15.0f;
    float fx = floorf(gx), fy = floorf(gy), fz = floorf(gz);
    float wx = gx - fx, wy = gy - fy, wz = gz - fz;
    int x0 = max(0, min(79, (int)fx));
    int y0 = max(0, min(59, (int)fy));
    int z0 = max(0, min(15, (int)fz));
    int packed3 = x0 | (y0 << 7) | (z0 << 13);
    g_s3[i] = make_float4(wx, wy, wz, __int_as_float(packed3));

    // 2D: W=160, H=120
    float hx = (px + 1.0f) * 0.5f * 159.0f;
    float hy = (py + 1.0f) * 0.5f * 119.0f;
    float fu = floorf(hx), fv = floorf(hy);
    float wu = hx - fu, wv = hy - fv;
    int u0 = max(0, min(159, (int)fu));
    int v0 = max(0, min(119, (int)fv));
    int packed2 = u0 | (v0 << 8);
    g_s2[i] = make_float4(wu, wv, __int_as_float(packed2), 0.0f);
}

// ---------------------------------------------------------------------------
// Main fused gather kernel, warp-dense version.
// Block = (b, x, y, z-half): 30 z-voxels x 200 channels.
// One WARP per z: lanes 0..24 each own 8 channels; each of the 12 taps is a
// single LDG.128 covering the voxel's full 400B channel row -> ~4 L1
// wavefronts per (z, tap) instead of ~10 in the per-item scheme.
// sAcc uses a skewed layout: channel c stored at column c + c/8 (lane stride
// 9 -> conflict-free scalar STS; phase-2 reads ~1-way).
// ---------------------------------------------------------------------------
__global__ void __launch_bounds__(256) flosp_kernel(float* __restrict__ out)
{
    __shared__ float sAcc[ZB * ASTR];   // [z][skewed c], 27 KB
    __shared__ int   sB[ZB * 12];       // tap base offsets (half-elements)
    __shared__ float sW[ZB * 12];       // tap weights

    int bid = blockIdx.x;
    int zh  = bid & 1;                  // z-half: z in [zh*30, zh*30+30)
    int t2  = bid >> 1;
    int y   = t2 % 36;
    int t3  = t2 / 36;
    int x   = t3 % 60;
    int bb  = t3 / 60;
    int tid = threadIdx.x;

    if (tid < ZB) {
        int z = zh * ZB + tid;
        int v = (x * 60 + z) * 36 + y;
        float4 s3 = g_s3[bb * NV + v];
        float4 s2 = g_s2[bb * NV + v];

        int p3 = __float_as_int(s3.w);
        int x0 = p3 & 127, y0 = (p3 >> 7) & 63, z0 = (p3 >> 13) & 15;
        float wx = s3.x, wy = s3.y, wz = s3.z;
        float ux = 1.0f - wx, uy = 1.0f - wy, uz = 1.0f - wz;
        int base3 = (bb * S3 + (z0 * 60 + y0) * 80 + x0) * NC;
        int ox = (x0 < 79) ? NC        : 0;
        int oy = (y0 < 59) ? 80 * NC   : 0;
        int oz = (z0 < 15) ? 4800 * NC : 0;
        #pragma unroll
        for (int i = 0; i < 8; i++) {
            int dx = i & 1, dy = (i >> 1) & 1, dz = (i >> 2) & 1;
            sB[tid * 12 + i] = base3 + (dx ? ox : 0) + (dy ? oy : 0) + (dz ? oz : 0);
            sW[tid * 12 + i] = (dx ? wx : ux) * (dy ? wy : uy) * (dz ? wz : uz);
        }

        int p2 = __float_as_int(s2.z);
        int u0 = p2 & 255, v0 = (p2 >> 8) & 127;
        float wu = s2.x, wv = s2.y;
        float nu = 1.0f - wu, nv = 1.0f - wv;
        int base2 = (bb * S2 + v0 * 160 + u0) * NC;
        int ou = (u0 < 159) ? NC       : 0;
        int ov = (v0 < 119) ? 160 * NC : 0;
        #pragma unroll
        for (int j = 0; j < 4; j++) {
            int dx = j & 1, dy = j >> 1;
            sB[tid * 12 + 8 + j] = base2 + (dx ? ou : 0) + (dy ? ov : 0);
            sW[tid * 12 + 8 + j] = (dx ? wu : nu) * (dy ? wv : nv);
        }
    }
    __syncthreads();

    // Phase 1: warp w handles z = p*8 + w; lane l<25 handles channels 8l..8l+7.
    int w = tid >> 5;
    int l = tid & 31;
    if (l < 25) {
        int c = 8 * l;
        #pragma unroll 1
        for (int p = 0; p < 4; p++) {
            int zi = p * 8 + w;
            if (zi >= ZB) break;
            const int*   Bv = sB + zi * 12;
            const float* Wv = sW + zi * 12;
            float a0 = 0.f, a1 = 0.f, a2 = 0.f, a3 = 0.f;
            float a4 = 0.f, a5 = 0.f, a6 = 0.f, a7 = 0.f;
            #pragma unroll
            for (int i = 0; i < 12; i++) {
                const __half* src = (i < 8) ? g_X3 : g_X2;
                uint4 r = *(const uint4*)(src + Bv[i] + c);   // LDG.128: 8 halfs
                float2 f0 = __half22float2(*(__half2*)&r.x);
                float2 f1 = __half22float2(*(__half2*)&r.y);
                float2 f2 = __half22float2(*(__half2*)&r.z);
                float2 f3 = __half22float2(*(__half2*)&r.w);
                float wt = Wv[i];
                a0 += wt * f0.x; a1 += wt * f0.y;
                a2 += wt * f1.x; a3 += wt * f1.y;
                a4 += wt * f2.x; a5 += wt * f2.y;
                a6 += wt * f3.x; a7 += wt * f3.y;
            }
            // Skewed store: channel c+k -> column c + c/8 + k = 9l + k
            float* dst = &sAcc[zi * ASTR + 9 * l];
            dst[0] = a0; dst[1] = a1; dst[2] = a2; dst[3] = a3;
            dst[4] = a4; dst[5] = a5; dst[6] = a6; dst[7] = a7;
        }
    }
    __syncthreads();

    // Phase 2: out[b][c][x][y][z], 15 float2 z-pairs per channel (30 z).
    int obase = bb * (NC * NV) + (x * 36 + y) * 60 + zh * ZB;
    for (int o = tid; o < 3000; o += 256) {
        int cl = o / 15;
        int zq = o - cl * 15;
        int sc = cl + (cl >> 3);        // skewed column
        float2 v = make_float2(sAcc[(2 * zq + 0) * ASTR + sc],
                               sAcc[(2 * zq + 1) * ASTR + sc]);
        *(float2*)&out[obase + cl * NV + 2 * zq] = v;
    }
}

// ---------------------------------------------------------------------------
extern "C" void kernel_launch(void* const* d_in, const int* in_sizes, int n_in,
                              void* d_out, int out_size)
{
    const float* x3a  = (const float*)d_in[0];
    const float* x3b  = (const float*)d_in[1];
    const float* x2a  = (const float*)d_in[2];
    const float* x2b  = (const float*)d_in[3];
    const float* proj = (const float*)d_in[4];
    float* out = (float*)d_out;

    dim3 tb(32, 8);
    sum_transpose_kernel<<<dim3(S3 / 32, 4, NB), tb>>>(x3a, x3b, S3, 0);
    sum_transpose_kernel<<<dim3(S2 / 32, 4, NB), tb>>>(x2a, x2b, S2, 1);
    prep_kernel<<<(NB * NV + 255) / 256, 256>>>(proj);
    flosp_kernel<<<NB * 60 * 36 * 2, 256>>>(out);
}